// round 15
// baseline (speedup 1.0000x reference)
#include <cuda_runtime.h>
#include <math.h>

// Problem constants (shapes fixed by setup_inputs)
#define H      1024
#define E      8
#define TOPK   2
#define NTOK   4096          // 2 * 2048
#define NSEL   (TOPK * NTOK) // 8192 selections, k-major order
#define NCHUNK 32            // 256 selections per chunk

// Scratch (device globals: allocation-free rule)
__device__ int   g_top1[NTOK];
__device__ int   g_top2[NTOK];
__device__ float g_p1[NTOK];
__device__ float g_p2[NTOK];
__device__ int   g_cnt[NCHUNK][E];   // zero-init; reset by k_scan each exec
__device__ int   g_off[NCHUNK][E];   // exclusive per-expert chunk offsets
__device__ float g_used[E];

// ---------------------------------------------------------------------------
// Gate kernel: one warp per token, w_g staged in smem; all 8 x-chunks loaded
// up front (MLP=8, evict-first) then FMA'd from registers against smem
// weights. Fused per-chunk per-expert selection counts via atomics.
// ---------------------------------------------------------------------------
__global__ __launch_bounds__(256) void k_gate(const float* __restrict__ x,
                                              const float* __restrict__ wg,
                                              int N) {
    __shared__ float s_wg[E * H];   // 32 KB
    for (int i = threadIdx.x; i < E * H; i += blockDim.x)
        s_wg[i] = wg[i];
    __syncthreads();

    int warp = threadIdx.x >> 5;
    int lane = threadIdx.x & 31;
    int token = blockIdx.x * 8 + warp;
    if (token >= N) return;

    const float4* x4 = reinterpret_cast<const float4*>(x + (size_t)token * H);

    // Batch-load the whole token row: 8 independent 16B loads in flight.
    float4 xv[8];
    #pragma unroll
    for (int c = 0; c < 8; c++)
        xv[c] = __ldcs(&x4[c * 32 + lane]);    // evict-first: don't pollute L2

    float acc[E];
    #pragma unroll
    for (int e = 0; e < E; e++) acc[e] = 0.f;

    #pragma unroll
    for (int c = 0; c < 8; c++) {
        int base = (c * 32 + lane) * 4;
        #pragma unroll
        for (int e = 0; e < E; e++) {
            float4 wv = *reinterpret_cast<const float4*>(&s_wg[e * H + base]);
            acc[e] += xv[c].x * wv.x + xv[c].y * wv.y
                    + xv[c].z * wv.z + xv[c].w * wv.w;
        }
    }
    #pragma unroll
    for (int e = 0; e < E; e++) {
        #pragma unroll
        for (int off = 16; off > 0; off >>= 1)
            acc[e] += __shfl_xor_sync(0xffffffffu, acc[e], off);
    }

    if (lane == 0) {
        int   i1 = 0; float l1 = acc[0];
        #pragma unroll
        for (int e = 1; e < E; e++)
            if (acc[e] > l1) { l1 = acc[e]; i1 = e; }
        int   i2 = -1; float l2 = -INFINITY;
        #pragma unroll
        for (int e = 0; e < E; e++)
            if (e != i1 && acc[e] > l2) { l2 = acc[e]; i2 = e; }

        float e2 = expf(l2 - l1);          // l1 >= l2
        float inv = 1.0f / (1.0f + e2);
        g_top1[token] = i1;
        g_top2[token] = i2;
        g_p1[token]   = inv;
        g_p2[token]   = e2 * inv;

        // chunk of selection s = k*NTOK + n  is  k*16 + (n>>8)
        int ch = token >> 8;
        atomicAdd(&g_cnt[ch][i1], 1);          // k = 0 selection
        atomicAdd(&g_cnt[16 + ch][i2], 1);     // k = 1 selection
    }
}

// ---------------------------------------------------------------------------
// Scan kernel: 1 block, 8 warps. Warp e shfl-scans the 32 chunk counts of
// expert e -> exclusive offsets + used_capacity; resets g_cnt for next exec.
// ---------------------------------------------------------------------------
__global__ __launch_bounds__(256) void k_scan(int C) {
    int e = threadIdx.x >> 5;      // expert (warp)
    int c = threadIdx.x & 31;      // chunk (lane)
    int v = g_cnt[c][e];
    int inc = v;
    #pragma unroll
    for (int off = 1; off < 32; off <<= 1) {
        int u = __shfl_up_sync(0xffffffffu, inc, off);
        if (c >= off) inc += u;
    }
    g_off[c][e] = inc - v;         // exclusive prefix
    if (c == 31)
        g_used[e] = (float)(inc < C ? inc : C);
    g_cnt[c][e] = 0;               // arm next execution
}

// ---------------------------------------------------------------------------
// Scatter kernel: 32 blocks x 1 warp; each warp replays its 256-selection
// chunk with ballots and scatters nonzeros (stores spread across 32 SMs).
// ---------------------------------------------------------------------------
__global__ __launch_bounds__(32) void k_scatter(float* __restrict__ out,
                                                int N, int C) {
    const int chunk = blockIdx.x;
    const int lane  = threadIdx.x;
    const unsigned lt = (1u << lane) - 1u;

    // broadcast base offsets: lane e<8 holds g_off[chunk][e]
    int offv = (lane < E) ? g_off[chunk][lane] : 0;

    float* cb  = out + E;
    float* msk = cb + (size_t)N * E * C;

    int run[E];
    #pragma unroll
    for (int e = 0; e < E; e++) run[e] = 0;

    #pragma unroll
    for (int i = 0; i < 8; i++) {
        int s = chunk * 256 + i * 32 + lane;
        int n = s & (NTOK - 1);
        int k = s >> 12;
        int e = k ? g_top2[n] : g_top1[n];
        float p = k ? g_p2[n] : g_p1[n];

        int myrank = 0;
        #pragma unroll
        for (int eid = 0; eid < E; eid++) {
            unsigned b = __ballot_sync(0xffffffffu, e == eid);
            if (e == eid) myrank = run[eid] + __popc(b & lt);
            run[eid] += __popc(b);
        }
        int rank = __shfl_sync(0xffffffffu, offv, e) + myrank;
        if (rank < C) {
            int idx = (n * E + e) * C + rank;    // < 67M, fits int
            cb[idx]  = p;
            msk[idx] = 1.0f;
        }
    }

    if (chunk == 0 && lane < E)
        out[lane] = g_used[lane];
}

// ---------------------------------------------------------------------------
extern "C" void kernel_launch(void* const* d_in, const int* in_sizes, int n_in,
                              void* d_out, int out_size) {
    const float* x  = (const float*)d_in[0];   // [2,2048,1024]
    const float* wg = (const float*)d_in[1];   // [8,1024]

    int N = in_sizes[0] / H;                           // 4096
    int cap = (int)(TOPK * 2.0 * N / E);               // 2048
    if (cap < 4) cap = 4;

    // Lazily create side stream + events (first call is the non-captured
    // correctness run, so creation never happens during graph capture).
    static cudaStream_t s2 = nullptr;
    static cudaEvent_t  evFork = nullptr, evJoin = nullptr;
    if (!s2) {
        cudaStreamCreateWithFlags(&s2, cudaStreamNonBlocking);
        cudaEventCreateWithFlags(&evFork, cudaEventDisableTiming);
        cudaEventCreateWithFlags(&evJoin, cudaEventDisableTiming);
    }

    // Fork: gate + scan on s2, concurrent with the big zeroing memset on the
    // capture stream. Join before the scatter (which writes into d_out).
    cudaEventRecord(evFork, 0);
    cudaStreamWaitEvent(s2, evFork, 0);

    k_gate<<<(N + 7) / 8, 256, 0, s2>>>(x, wg, N);
    k_scan<<<1, 256, 0, s2>>>(cap);
    cudaEventRecord(evJoin, s2);

    // Zero the whole (poisoned) output: the DRAM-write floor.
    cudaMemsetAsync(d_out, 0, (size_t)out_size * sizeof(float), 0);

    cudaStreamWaitEvent(0, evJoin, 0);
    k_scatter<<<NCHUNK, 32>>>((float*)d_out, N, cap);
}

// round 17
// speedup vs baseline: 1.0164x; 1.0164x over previous
#include <cuda_runtime.h>
#include <math.h>

// Problem constants (shapes fixed by setup_inputs)
#define H      1024
#define E      8
#define TOPK   2
#define NTOK   4096          // 2 * 2048
#define NSEL   (TOPK * NTOK) // 8192 selections, k-major order
#define NCHUNK 32            // 256 selections per chunk

// Scratch (device globals: allocation-free rule)
__device__ int   g_top1[NTOK];
__device__ int   g_top2[NTOK];
__device__ float g_p1[NTOK];
__device__ float g_p2[NTOK];
__device__ int   g_cnt[NCHUNK][E];   // zero-init; reset by k_scan each exec
__device__ int   g_off[NCHUNK][E];   // exclusive per-expert chunk offsets
__device__ float g_used[E];

// ---------------------------------------------------------------------------
// Gate kernel: 2 tokens per warp (weight LDS amortized 2x -> 16KB/token),
// x loaded in two batched halves (MLP=8, evict-first). w_g staged in smem.
// Fused per-chunk per-expert selection counts via atomics. grid = 256.
// ---------------------------------------------------------------------------
__global__ __launch_bounds__(256) void k_gate(const float* __restrict__ x,
                                              const float* __restrict__ wg,
                                              int N) {
    __shared__ float s_wg[E * H];   // 32 KB
    for (int i = threadIdx.x; i < E * H; i += blockDim.x)
        s_wg[i] = wg[i];
    __syncthreads();

    int warp = threadIdx.x >> 5;
    int lane = threadIdx.x & 31;
    int t0 = (blockIdx.x * 8 + warp) * 2;       // 2 consecutive tokens

    const float4* xA = reinterpret_cast<const float4*>(x + (size_t)t0 * H);
    const float4* xB = xA + (H / 4);

    float acc0[E], acc1[E];
    #pragma unroll
    for (int e = 0; e < E; e++) { acc0[e] = 0.f; acc1[e] = 0.f; }

    #pragma unroll
    for (int half = 0; half < 2; half++) {
        // Batch 8 independent loads (2 tokens x 4 chunks), evict-first.
        float4 a[4], b[4];
        #pragma unroll
        for (int c = 0; c < 4; c++) {
            int idx4 = (half * 4 + c) * 32 + lane;
            a[c] = __ldcs(&xA[idx4]);
            b[c] = __ldcs(&xB[idx4]);
        }
        #pragma unroll
        for (int c = 0; c < 4; c++) {
            int base = ((half * 4 + c) * 32 + lane) * 4;
            #pragma unroll
            for (int e = 0; e < E; e++) {
                float4 wv = *reinterpret_cast<const float4*>(&s_wg[e * H + base]);
                acc0[e] += a[c].x * wv.x + a[c].y * wv.y
                         + a[c].z * wv.z + a[c].w * wv.w;
                acc1[e] += b[c].x * wv.x + b[c].y * wv.y
                         + b[c].z * wv.z + b[c].w * wv.w;
            }
        }
    }

    #pragma unroll
    for (int e = 0; e < E; e++) {
        #pragma unroll
        for (int off = 16; off > 0; off >>= 1) {
            acc0[e] += __shfl_xor_sync(0xffffffffu, acc0[e], off);
            acc1[e] += __shfl_xor_sync(0xffffffffu, acc1[e], off);
        }
    }

    if (lane < 2) {
        int token = t0 + lane;
        float l[E];
        #pragma unroll
        for (int e = 0; e < E; e++) l[e] = lane ? acc1[e] : acc0[e];
        int   i1 = 0; float l1 = l[0];
        #pragma unroll
        for (int e = 1; e < E; e++)
            if (l[e] > l1) { l1 = l[e]; i1 = e; }
        int   i2 = -1; float l2 = -INFINITY;
        #pragma unroll
        for (int e = 0; e < E; e++)
            if (e != i1 && l[e] > l2) { l2 = l[e]; i2 = e; }

        float e2 = expf(l2 - l1);          // l1 >= l2
        float inv = 1.0f / (1.0f + e2);
        g_top1[token] = i1;
        g_top2[token] = i2;
        g_p1[token]   = inv;
        g_p2[token]   = e2 * inv;

        // chunk of selection s = k*NTOK + n  is  k*16 + (n>>8)
        int ch = token >> 8;
        atomicAdd(&g_cnt[ch][i1], 1);          // k = 0 selection
        atomicAdd(&g_cnt[16 + ch][i2], 1);     // k = 1 selection
    }
}

// ---------------------------------------------------------------------------
// Scan kernel: 1 block, 8 warps. Warp e shfl-scans the 32 chunk counts of
// expert e -> exclusive offsets + used_capacity; resets g_cnt for next exec.
// ---------------------------------------------------------------------------
__global__ __launch_bounds__(256) void k_scan(int C) {
    int e = threadIdx.x >> 5;      // expert (warp)
    int c = threadIdx.x & 31;      // chunk (lane)
    int v = g_cnt[c][e];
    int inc = v;
    #pragma unroll
    for (int off = 1; off < 32; off <<= 1) {
        int u = __shfl_up_sync(0xffffffffu, inc, off);
        if (c >= off) inc += u;
    }
    g_off[c][e] = inc - v;         // exclusive prefix
    if (c == 31)
        g_used[e] = (float)(inc < C ? inc : C);
    g_cnt[c][e] = 0;               // arm next execution
}

// ---------------------------------------------------------------------------
// Scatter kernel: 32 blocks x 1 warp; each warp replays its 256-selection
// chunk with ballots and scatters nonzeros (stores spread across 32 SMs).
// ---------------------------------------------------------------------------
__global__ __launch_bounds__(32) void k_scatter(float* __restrict__ out,
                                                int N, int C) {
    const int chunk = blockIdx.x;
    const int lane  = threadIdx.x;
    const unsigned lt = (1u << lane) - 1u;

    // broadcast base offsets: lane e<8 holds g_off[chunk][e]
    int offv = (lane < E) ? g_off[chunk][lane] : 0;

    float* cb  = out + E;
    float* msk = cb + (size_t)N * E * C;

    int run[E];
    #pragma unroll
    for (int e = 0; e < E; e++) run[e] = 0;

    #pragma unroll
    for (int i = 0; i < 8; i++) {
        int s = chunk * 256 + i * 32 + lane;
        int n = s & (NTOK - 1);
        int k = s >> 12;
        int e = k ? g_top2[n] : g_top1[n];
        float p = k ? g_p2[n] : g_p1[n];

        int myrank = 0;
        #pragma unroll
        for (int eid = 0; eid < E; eid++) {
            unsigned b = __ballot_sync(0xffffffffu, e == eid);
            if (e == eid) myrank = run[eid] + __popc(b & lt);
            run[eid] += __popc(b);
        }
        int rank = __shfl_sync(0xffffffffu, offv, e) + myrank;
        if (rank < C) {
            int idx = (n * E + e) * C + rank;    // < 67M, fits int
            cb[idx]  = p;
            msk[idx] = 1.0f;
        }
    }

    if (chunk == 0 && lane < E)
        out[lane] = g_used[lane];
}

// ---------------------------------------------------------------------------
extern "C" void kernel_launch(void* const* d_in, const int* in_sizes, int n_in,
                              void* d_out, int out_size) {
    const float* x  = (const float*)d_in[0];   // [2,2048,1024]
    const float* wg = (const float*)d_in[1];   // [8,1024]

    int N = in_sizes[0] / H;                           // 4096
    int cap = (int)(TOPK * 2.0 * N / E);               // 2048
    if (cap < 4) cap = 4;

    // Lazily create side stream + events (first call is the non-captured
    // correctness run, so creation never happens during graph capture).
    static cudaStream_t s2 = nullptr;
    static cudaEvent_t  evFork = nullptr, evJoin = nullptr;
    if (!s2) {
        cudaStreamCreateWithFlags(&s2, cudaStreamNonBlocking);
        cudaEventCreateWithFlags(&evFork, cudaEventDisableTiming);
        cudaEventCreateWithFlags(&evJoin, cudaEventDisableTiming);
    }

    // Fork: gate + scan on s2, concurrent with the big zeroing memset on the
    // capture stream. Join before the scatter (which writes into d_out).
    cudaEventRecord(evFork, 0);
    cudaStreamWaitEvent(s2, evFork, 0);

    k_gate<<<NTOK / 16, 256, 0, s2>>>(x, wg, N);
    k_scan<<<1, 256, 0, s2>>>(cap);
    cudaEventRecord(evJoin, s2);

    // Zero the whole (poisoned) output: the DRAM-write floor.
    cudaMemsetAsync(d_out, 0, (size_t)out_size * sizeof(float), 0);

    cudaStreamWaitEvent(0, evJoin, 0);
    k_scatter<<<NCHUNK, 32>>>((float*)d_out, N, cap);
}